// round 2
// baseline (speedup 1.0000x reference)
#include <cuda_runtime.h>
#include <cstdint>

// Flash-attention fp32, B=4,H=16,S=2048,D=128, scale = 1/0.32 = 3.125
// R2: packed fma.rn.f32x2 for both GEMMs + cp.async prefetch of K/V tiles.
// Grid: (S/BM, B*H). 256 threads/CTA, 1 CTA/SM.

#define BM 128
#define BN 64
#define DD 128
#define DP 132          // padded row stride (floats) for Q/K/V
#define PD2 136         // padded row stride (floats) for duplicated P (128 data + 8 pad)
#define NTHREADS 256
#define SEQ 2048
#define NT (SEQ/BN)     // 32 tiles
#define SCALE_INV 3.125f

typedef unsigned long long u64;

static constexpr int SMEM_FLOATS = BM*DP + BN*DP + BN*DP + BM*PD2 + 3*BM;
static constexpr int SMEM_BYTES  = SMEM_FLOATS * 4;   // ~201.5 KB

#define FMA2(d, a, b) asm("fma.rn.f32x2 %0, %1, %2, %0;" : "+l"(d) : "l"(a), "l"(b))
#define MUL2(d, a, b) asm("mul.rn.f32x2 %0, %1, %2;" : "=l"(d) : "l"(a), "l"(b))

__device__ __forceinline__ u64 pack_dup(float x) {
    u64 r; unsigned u = __float_as_uint(x);
    asm("mov.b64 %0, {%1, %1};" : "=l"(r) : "r"(u));
    return r;
}
__device__ __forceinline__ float lo_f(u64 v) { return __uint_as_float((unsigned)v); }
__device__ __forceinline__ float hi_f(u64 v) { return __uint_as_float((unsigned)(v >> 32)); }

#define CP_ASYNC16(dst_u32, src) \
    asm volatile("cp.async.cg.shared.global [%0], [%1], 16;" :: "r"(dst_u32), "l"(src))
#define CP_COMMIT() asm volatile("cp.async.commit_group;")
#define CP_WAIT1()  asm volatile("cp.async.wait_group 1;")
#define CP_WAIT0()  asm volatile("cp.async.wait_group 0;")

__global__ __launch_bounds__(NTHREADS, 1)
void fa_fp32_kernel(const float* __restrict__ Qg, const float* __restrict__ Kg,
                    const float* __restrict__ Vg, float* __restrict__ Og) {
    extern __shared__ float sm[];
    float* sQ  = sm;                 // [BM][DP]
    float* sK  = sQ + BM*DP;         // [BN][DP]
    float* sV  = sK + BN*DP;         // [BN][DP]
    float* sPd = sV + BN*DP;         // [BM][PD2]  duplicated P: (p,p) pairs
    float* sM  = sPd + BM*PD2;       // [BM]
    float* sL  = sM + BM;            // [BM]
    float* sA  = sL + BM;            // [BM]

    const int tid = threadIdx.x;
    const int tx  = tid & 15;
    const int ty  = tid >> 4;

    const size_t hoff = (size_t)blockIdx.y * SEQ * DD;
    const float* Qh = Qg + hoff + (size_t)blockIdx.x * BM * DD;
    const float* Kh = Kg + hoff;
    const float* Vh = Vg + hoff;
    float*       Oh = Og + hoff + (size_t)blockIdx.x * BM * DD;

    // ---- prefetch K(0), V(0) via cp.async (each thread: 8 float4 per tile) ----
    {
        const float4* K4 = (const float4*)Kh;
        #pragma unroll
        for (int t = 0; t < 8; t++) {
            int i  = tid + t * NTHREADS;
            int r  = i >> 5, c4 = i & 31;
            uint32_t dst = (uint32_t)__cvta_generic_to_shared(sK + r*DP + c4*4);
            CP_ASYNC16(dst, K4 + i);
        }
        CP_COMMIT();
        const float4* V4 = (const float4*)Vh;
        #pragma unroll
        for (int t = 0; t < 8; t++) {
            int i  = tid + t * NTHREADS;
            int r  = i >> 5, c4 = i & 31;
            uint32_t dst = (uint32_t)__cvta_generic_to_shared(sV + r*DP + c4*4);
            CP_ASYNC16(dst, V4 + i);
        }
        CP_COMMIT();
    }

    // ---- load Q tile (plain, overlaps with async K/V fetch) ----
    for (int i = tid; i < BM * (DD/4); i += NTHREADS) {
        int r = i >> 5, c4 = i & 31;
        ((float4*)(sQ + r*DP))[c4] = ((const float4*)Qh)[i];
    }
    if (tid < BM) { sM[tid] = -1e30f; sL[tid] = 0.0f; }

    u64 oacc[8][4];   // packed over column pairs: cols (tx*8+2jp, tx*8+2jp+1)
    #pragma unroll
    for (int i = 0; i < 8; i++)
        #pragma unroll
        for (int j = 0; j < 4; j++) oacc[i][j] = 0ULL;

    for (int kt = 0; kt < NT; kt++) {
        CP_WAIT1();          // K(kt) complete (V(kt) may still be in flight)
        __syncthreads();

        // ---- S = Q*K^T, packed along k ----
        u64 sacc[8][4];
        #pragma unroll
        for (int i = 0; i < 8; i++)
            #pragma unroll
            for (int j = 0; j < 4; j++) sacc[i][j] = 0ULL;

        #pragma unroll 2
        for (int k0 = 0; k0 < DD; k0 += 4) {     // 2 packed pairs per iter
            ulonglong2 q2[8];
            #pragma unroll
            for (int i = 0; i < 8; i++)
                q2[i] = *(const ulonglong2*)(sQ + (ty*8 + i)*DP + k0);
            ulonglong2 k2[4];
            #pragma unroll
            for (int j = 0; j < 4; j++)
                k2[j] = *(const ulonglong2*)(sK + (tx + 16*j)*DP + k0);
            #pragma unroll
            for (int i = 0; i < 8; i++)
                #pragma unroll
                for (int j = 0; j < 4; j++) {
                    FMA2(sacc[i][j], q2[i].x, k2[j].x);
                    FMA2(sacc[i][j], q2[i].y, k2[j].y);
                }
        }
        // horizontal add + scale, store duplicated (s,s)
        #pragma unroll
        for (int i = 0; i < 8; i++)
            #pragma unroll
            for (int j = 0; j < 4; j++) {
                float s = (lo_f(sacc[i][j]) + hi_f(sacc[i][j])) * SCALE_INV;
                *(float2*)(sPd + (ty*8 + i)*PD2 + 2*(tx + 16*j)) = make_float2(s, s);
            }
        __syncthreads();

        // ---- prefetch K(kt+1): all QK reads of sK are done ----
        if (kt + 1 < NT) {
            const float4* K4 = (const float4*)(Kh + (size_t)(kt+1) * BN * DD);
            #pragma unroll
            for (int t = 0; t < 8; t++) {
                int i  = tid + t * NTHREADS;
                int r  = i >> 5, c4 = i & 31;
                uint32_t dst = (uint32_t)__cvta_generic_to_shared(sK + r*DP + c4*4);
                CP_ASYNC16(dst, K4 + i);
            }
            CP_COMMIT();
        }

        // ---- online softmax per row (threads 0..127) ----
        if (tid < BM) {
            float* row = sPd + tid*PD2;
            float mo = sM[tid];
            float mx = mo;
            #pragma unroll 8
            for (int j = 0; j < BN; j++) mx = fmaxf(mx, row[2*j]);
            float alpha = __expf(mo - mx);
            float sum = 0.0f;
            #pragma unroll 8
            for (int j = 0; j < BN; j++) {
                float p = __expf(row[2*j] - mx);
                *(float2*)(row + 2*j) = make_float2(p, p);
                sum += p;
            }
            sM[tid] = mx;
            sL[tid] = sL[tid]*alpha + sum;
            sA[tid] = alpha;
        }
        // V(kt) must be complete before PV. Pending after QK commit:
        //   {V(kt), K(kt+1)} -> wait 1 leaves K(kt+1) in flight. Last tile: {V(kt)} -> wait 0.
        if (kt + 1 < NT) { CP_WAIT1(); } else { CP_WAIT0(); }
        __syncthreads();

        // ---- O = O*alpha + P @ V, packed over column pairs ----
        #pragma unroll
        for (int i = 0; i < 8; i++) {
            u64 al2 = pack_dup(sA[ty*8 + i]);
            #pragma unroll
            for (int j = 0; j < 4; j++) MUL2(oacc[i][j], oacc[i][j], al2);
        }

        #pragma unroll 2
        for (int kk = 0; kk < BN; kk += 2) {
            ulonglong2 pp[8];   // (p_kk dup, p_kk+1 dup)
            #pragma unroll
            for (int i = 0; i < 8; i++)
                pp[i] = *(const ulonglong2*)(sPd + (ty*8 + i)*PD2 + 2*kk);
            ulonglong2 v0a = *(const ulonglong2*)(sV + kk*DP + tx*8);
            ulonglong2 v0b = *(const ulonglong2*)(sV + kk*DP + tx*8 + 4);
            ulonglong2 v1a = *(const ulonglong2*)(sV + (kk+1)*DP + tx*8);
            ulonglong2 v1b = *(const ulonglong2*)(sV + (kk+1)*DP + tx*8 + 4);
            #pragma unroll
            for (int i = 0; i < 8; i++) {
                FMA2(oacc[i][0], pp[i].x, v0a.x);
                FMA2(oacc[i][1], pp[i].x, v0a.y);
                FMA2(oacc[i][2], pp[i].x, v0b.x);
                FMA2(oacc[i][3], pp[i].x, v0b.y);
                FMA2(oacc[i][0], pp[i].y, v1a.x);
                FMA2(oacc[i][1], pp[i].y, v1a.y);
                FMA2(oacc[i][2], pp[i].y, v1b.x);
                FMA2(oacc[i][3], pp[i].y, v1b.y);
            }
        }
        __syncthreads();

        // ---- prefetch V(kt+1): all PV reads of sV are done ----
        if (kt + 1 < NT) {
            const float4* V4 = (const float4*)(Vh + (size_t)(kt+1) * BN * DD);
            #pragma unroll
            for (int t = 0; t < 8; t++) {
                int i  = tid + t * NTHREADS;
                int r  = i >> 5, c4 = i & 31;
                uint32_t dst = (uint32_t)__cvta_generic_to_shared(sV + r*DP + c4*4);
                CP_ASYNC16(dst, V4 + i);
            }
            CP_COMMIT();
        }
    }

    // ---- finalize ----
    float li[8];
    #pragma unroll
    for (int i = 0; i < 8; i++) li[i] = 1.0f / sL[ty*8 + i];
    #pragma unroll
    for (int i = 0; i < 8; i++) {
        float4 o0, o1;
        o0.x = lo_f(oacc[i][0])*li[i]; o0.y = hi_f(oacc[i][0])*li[i];
        o0.z = lo_f(oacc[i][1])*li[i]; o0.w = hi_f(oacc[i][1])*li[i];
        o1.x = lo_f(oacc[i][2])*li[i]; o1.y = hi_f(oacc[i][2])*li[i];
        o1.z = lo_f(oacc[i][3])*li[i]; o1.w = hi_f(oacc[i][3])*li[i];
        *(float4*)(Oh + (ty*8 + i)*DD + tx*8)     = o0;
        *(float4*)(Oh + (ty*8 + i)*DD + tx*8 + 4) = o1;
    }
}

extern "C" void kernel_launch(void* const* d_in, const int* in_sizes, int n_in,
                              void* d_out, int out_size) {
    const float* Q = (const float*)d_in[0];
    const float* K = (const float*)d_in[1];
    const float* V = (const float*)d_in[2];
    float* O = (float*)d_out;

    cudaFuncSetAttribute(fa_fp32_kernel,
                         cudaFuncAttributeMaxDynamicSharedMemorySize, SMEM_BYTES);

    dim3 grid(SEQ / BM, 64 /* B*H */);
    fa_fp32_kernel<<<grid, NTHREADS, SMEM_BYTES>>>(Q, K, V, O);
}

// round 7
// speedup vs baseline: 2.8509x; 2.8509x over previous
#include <cuda_runtime.h>
#include <cuda_bf16.h>
#include <cstdint>

// mma.sync (Ampere-path) bf16 3-pass flash attention for sm_103 baseline target.
// B=4,H=16,S=2048,D=128, scale=1/0.32. Grid (16,64), 256 threads, 8 warps.

#define SEQ 2048
#define DD 128
#define BM 128
#define BN 64
#define NT (SEQ/BN)
#define NTH 256
#define SCALE_INV 3.125f

#define SM_QHI 0
#define SM_QLO 32768
#define SM_KHI 65536
#define SM_KLO 81920
#define SM_VHI 98304
#define SM_VLO 114688
#define SM_TOTAL 131072

typedef uint32_t u32;

__device__ __forceinline__ u32 smem_u32(const void* p) {
    u32 a; asm("{ .reg .u64 t; cvta.to.shared.u64 t, %1; cvt.u32.u64 %0, t; }" : "=r"(a) : "l"(p));
    return a;
}

// Swizzled byte offset inside a [R rows][128 bf16] tile stored as 8-row x 64-col
// (1KB) atoms, panel-major in col, SW128 within atom. rshift: log2(R/8).
__device__ __forceinline__ u32 swz(int row, int col, int rshift) {
    u32 atom   = (u32)((row >> 3) + ((col >> 6) << rshift));
    u32 coloff = ((u32)(col & 63) * 2u) ^ (((u32)row & 7u) << 4);
    return atom * 1024u + ((u32)row & 7u) * 128u + coloff;
}

__device__ __forceinline__ void split2(float a, float b, u32& hi, u32& lo) {
    unsigned short ha = __bfloat16_as_ushort(__float2bfloat16(a));
    unsigned short hb = __bfloat16_as_ushort(__float2bfloat16(b));
    float ra = a - __bfloat162float(__ushort_as_bfloat16(ha));
    float rb = b - __bfloat162float(__ushort_as_bfloat16(hb));
    unsigned short la = __bfloat16_as_ushort(__float2bfloat16(ra));
    unsigned short lb = __bfloat16_as_ushort(__float2bfloat16(rb));
    hi = ((u32)hb << 16) | ha;
    lo = ((u32)lb << 16) | la;
}

#define LDSM4(r, a) \
    asm volatile("ldmatrix.sync.aligned.m8n8.x4.shared.b16 {%0,%1,%2,%3}, [%4];" \
        : "=r"((r)[0]), "=r"((r)[1]), "=r"((r)[2]), "=r"((r)[3]) : "r"(a))
#define LDSM4T(r, a) \
    asm volatile("ldmatrix.sync.aligned.m8n8.x4.trans.shared.b16 {%0,%1,%2,%3}, [%4];" \
        : "=r"((r)[0]), "=r"((r)[1]), "=r"((r)[2]), "=r"((r)[3]) : "r"(a))
#define MMA(c, a, b0, b1) \
    asm volatile("mma.sync.aligned.m16n8k16.row.col.f32.bf16.bf16.f32 " \
        "{%0,%1,%2,%3}, {%4,%5,%6,%7}, {%8,%9}, {%0,%1,%2,%3};" \
        : "+f"((c)[0]), "+f"((c)[1]), "+f"((c)[2]), "+f"((c)[3]) \
        : "r"((a)[0]), "r"((a)[1]), "r"((a)[2]), "r"((a)[3]), "r"(b0), "r"(b1))

__global__ __launch_bounds__(NTH, 1)
void fa_mma_kernel(const float* __restrict__ Qg, const float* __restrict__ Kg,
                   const float* __restrict__ Vg, float* __restrict__ Og) {
    extern __shared__ char smem[];
    const u32 sb = smem_u32(smem);
    const int tid = threadIdx.x, wid = tid >> 5, lane = tid & 31;

    const size_t hoff = (size_t)blockIdx.y * SEQ * DD;
    const float* Qh = Qg + hoff + (size_t)blockIdx.x * BM * DD;
    const float* Kh = Kg + hoff;
    const float* Vh = Vg + hoff;
    float*       Oh = Og + hoff + (size_t)blockIdx.x * BM * DD;

    // ---- Q tile fill: fp32 -> bf16 hi/lo, swizzled ----
    {
        const float4* G4 = (const float4*)Qh;
        #pragma unroll
        for (int t = 0; t < 16; t++) {
            int i = tid + t * NTH;
            int row = i >> 5, col0 = (i & 31) * 4;
            float4 v = G4[i];
            u32 h0, l0, h1, l1;
            split2(v.x, v.y, h0, l0);
            split2(v.z, v.w, h1, l1);
            u32 a = swz(row, col0, 4);
            *(uint2*)(smem + SM_QHI + a) = make_uint2(h0, h1);
            *(uint2*)(smem + SM_QLO + a) = make_uint2(l0, l1);
        }
    }

    float oacc[16][4];
    #pragma unroll
    for (int n = 0; n < 16; n++)
        #pragma unroll
        for (int c = 0; c < 4; c++) oacc[n][c] = 0.0f;

    float m0 = -1e30f, m1 = -1e30f, l0s = 0.0f, l1s = 0.0f;

    // ldmatrix per-lane address components
    const int frow  = (lane & 7) + ((lane >> 3) & 1) * 8;  // row within 16-tile
    const int fcol8 = ((lane >> 4) & 1) * 8;               // k/col half
    const int qrow  = wid * 16 + frow;

    for (int kt = 0; kt < NT; kt++) {
        // ---- K,V tile fill ----
        const float4* K4 = (const float4*)(Kh + (size_t)kt * BN * DD);
        const float4* V4 = (const float4*)(Vh + (size_t)kt * BN * DD);
        #pragma unroll
        for (int t = 0; t < 8; t++) {
            int i = tid + t * NTH;
            int row = i >> 5, col0 = (i & 31) * 4;
            u32 a = swz(row, col0, 3);
            float4 v = K4[i];
            u32 h0, lo0, h1, lo1;
            split2(v.x, v.y, h0, lo0);
            split2(v.z, v.w, h1, lo1);
            *(uint2*)(smem + SM_KHI + a) = make_uint2(h0, h1);
            *(uint2*)(smem + SM_KLO + a) = make_uint2(lo0, lo1);
            float4 w = V4[i];
            split2(w.x, w.y, h0, lo0);
            split2(w.z, w.w, h1, lo1);
            *(uint2*)(smem + SM_VHI + a) = make_uint2(h0, h1);
            *(uint2*)(smem + SM_VLO + a) = make_uint2(lo0, lo1);
        }
        __syncthreads();

        // ---- S = Q K^T : 3 passes (Ah*Bh, Al*Bh, Ah*Bl) ----
        float sacc[8][4];
        #pragma unroll
        for (int j = 0; j < 8; j++)
            #pragma unroll
            for (int c = 0; c < 4; c++) sacc[j][c] = 0.0f;

        #pragma unroll
        for (int kk = 0; kk < 8; kk++) {
            u32 ah[4], al[4];
            u32 qa = sb + SM_QHI + swz(qrow, kk * 16 + fcol8, 4);
            LDSM4(ah, qa);
            LDSM4(al, qa + (SM_QLO - SM_QHI));
            u32 bh[16], bl[16];
            #pragma unroll
            for (int ng = 0; ng < 4; ng++) {
                u32 ka = sb + SM_KHI + swz(ng * 16 + frow, kk * 16 + fcol8, 3);
                LDSM4(bh + 4 * ng, ka);
                LDSM4(bl + 4 * ng, ka + (SM_KLO - SM_KHI));
            }
            #pragma unroll
            for (int j = 0; j < 8; j++) {
                u32 h0 = bh[4 * (j >> 1) + (j & 1)], h1 = bh[4 * (j >> 1) + 2 + (j & 1)];
                u32 q0 = bl[4 * (j >> 1) + (j & 1)], q1 = bl[4 * (j >> 1) + 2 + (j & 1)];
                MMA(sacc[j], ah, h0, h1);
                MMA(sacc[j], al, h0, h1);
                MMA(sacc[j], ah, q0, q1);
            }
        }

        // ---- online softmax (rows r0 = lane>>2, r0+8 of this warp's 16) ----
        float mx0 = m0, mx1 = m1;
        #pragma unroll
        for (int j = 0; j < 8; j++) {
            mx0 = fmaxf(mx0, fmaxf(sacc[j][0], sacc[j][1]));
            mx1 = fmaxf(mx1, fmaxf(sacc[j][2], sacc[j][3]));
        }
        mx0 = fmaxf(mx0, __shfl_xor_sync(0xffffffffu, mx0, 1));
        mx0 = fmaxf(mx0, __shfl_xor_sync(0xffffffffu, mx0, 2));
        mx1 = fmaxf(mx1, __shfl_xor_sync(0xffffffffu, mx1, 1));
        mx1 = fmaxf(mx1, __shfl_xor_sync(0xffffffffu, mx1, 2));
        float alpha0 = __expf((m0 - mx0) * SCALE_INV);
        float alpha1 = __expf((m1 - mx1) * SCALE_INV);

        float sum0 = 0.0f, sum1 = 0.0f;
        u32 ph[8][2], pl[8][2];
        #pragma unroll
        for (int j = 0; j < 8; j++) {
            float p0 = __expf((sacc[j][0] - mx0) * SCALE_INV);
            float p1 = __expf((sacc[j][1] - mx0) * SCALE_INV);
            float p2 = __expf((sacc[j][2] - mx1) * SCALE_INV);
            float p3 = __expf((sacc[j][3] - mx1) * SCALE_INV);
            sum0 += p0 + p1;
            sum1 += p2 + p3;
            split2(p0, p1, ph[j][0], pl[j][0]);
            split2(p2, p3, ph[j][1], pl[j][1]);
        }
        sum0 += __shfl_xor_sync(0xffffffffu, sum0, 1);
        sum0 += __shfl_xor_sync(0xffffffffu, sum0, 2);
        sum1 += __shfl_xor_sync(0xffffffffu, sum1, 1);
        sum1 += __shfl_xor_sync(0xffffffffu, sum1, 2);
        l0s = l0s * alpha0 + sum0;
        l1s = l1s * alpha1 + sum1;
        m0 = mx0; m1 = mx1;

        // ---- O *= alpha ----
        #pragma unroll
        for (int n = 0; n < 16; n++) {
            oacc[n][0] *= alpha0; oacc[n][1] *= alpha0;
            oacc[n][2] *= alpha1; oacc[n][3] *= alpha1;
        }

        // ---- O += P V : 3 passes (Ph*Vh, Pl*Vh, Ph*Vl) ----
        #pragma unroll
        for (int kk = 0; kk < 4; kk++) {
            u32 pah[4] = {ph[2*kk][0], ph[2*kk][1], ph[2*kk+1][0], ph[2*kk+1][1]};
            u32 pal[4] = {pl[2*kk][0], pl[2*kk][1], pl[2*kk+1][0], pl[2*kk+1][1]};
            #pragma unroll
            for (int ng = 0; ng < 8; ng++) {
                u32 vh4[4], vl4[4];
                u32 va = sb + SM_VHI + swz(kk * 16 + frow, ng * 16 + fcol8, 3);
                LDSM4T(vh4, va);
                LDSM4T(vl4, va + (SM_VLO - SM_VHI));
                // ntile 2ng: {r0,r1}; ntile 2ng+1: {r2,r3}
                MMA(oacc[2*ng],     pah, vh4[0], vh4[1]);
                MMA(oacc[2*ng],     pal, vh4[0], vh4[1]);
                MMA(oacc[2*ng],     pah, vl4[0], vl4[1]);
                MMA(oacc[2*ng + 1], pah, vh4[2], vh4[3]);
                MMA(oacc[2*ng + 1], pal, vh4[2], vh4[3]);
                MMA(oacc[2*ng + 1], pah, vl4[2], vl4[3]);
            }
        }
        __syncthreads();
    }

    // ---- epilogue: normalize + store ----
    float inv0 = 1.0f / l0s, inv1 = 1.0f / l1s;
    int orow0 = wid * 16 + (lane >> 2);
    int orow1 = orow0 + 8;
    #pragma unroll
    for (int n = 0; n < 16; n++) {
        int col = n * 8 + 2 * (lane & 3);
        *(float2*)(Oh + (size_t)orow0 * DD + col) = make_float2(oacc[n][0] * inv0, oacc[n][1] * inv0);
        *(float2*)(Oh + (size_t)orow1 * DD + col) = make_float2(oacc[n][2] * inv1, oacc[n][3] * inv1);
    }
}

extern "C" void kernel_launch(void* const* d_in, const int* in_sizes, int n_in,
                              void* d_out, int out_size) {
    const float* Q = (const float*)d_in[0];
    const float* K = (const float*)d_in[1];
    const float* V = (const float*)d_in[2];
    float* O = (float*)d_out;

    cudaFuncSetAttribute(fa_mma_kernel,
                         cudaFuncAttributeMaxDynamicSharedMemorySize, SM_TOTAL);

    dim3 grid(SEQ / BM, 64 /* B*H */);
    fa_mma_kernel<<<grid, NTH, SM_TOTAL>>>(Q, K, V, O);
}

// round 8
// speedup vs baseline: 3.0304x; 1.0630x over previous
#include <cuda_runtime.h>
#include <cuda_bf16.h>
#include <cstdint>

// mma.sync bf16 3-pass flash attention, cp.async-staged K/V, double-buffered frags.
// B=4,H=16,S=2048,D=128, scale=1/0.32. Grid (16,64), 256 threads, 8 warps.

#define SEQ 2048
#define DD 128
#define BM 128
#define BN 64
#define NT (SEQ/BN)
#define NTH 256
#define SCALE_INV 3.125f

// smem byte offsets
#define SM_QHI 0
#define SM_QLO 32768
#define SM_KHI 65536
#define SM_KLO 81920
#define SM_VHI 98304
#define SM_VLO 114688
#define SM_STG 131072          // raw fp32 staging: K 32KB then V 32KB
#define SM_TOTAL 196608        // 192KB

typedef uint32_t u32;

__device__ __forceinline__ u32 smem_u32(const void* p) {
    u32 a; asm("{ .reg .u64 t; cvta.to.shared.u64 t, %1; cvt.u32.u64 %0, t; }" : "=r"(a) : "l"(p));
    return a;
}

// Swizzled byte offset in a [R rows][128 bf16] tile: 8-row x 64-col (1KB) atoms,
// panel-major in col, SW128 within atom. rshift = log2(R/8).
__device__ __forceinline__ u32 swz(int row, int col, int rshift) {
    u32 atom   = (u32)((row >> 3) + ((col >> 6) << rshift));
    u32 coloff = ((u32)(col & 63) * 2u) ^ (((u32)row & 7u) << 4);
    return atom * 1024u + ((u32)row & 7u) * 128u + coloff;
}

__device__ __forceinline__ void split2(float a, float b, u32& hi, u32& lo) {
    unsigned short ha = __bfloat16_as_ushort(__float2bfloat16(a));
    unsigned short hb = __bfloat16_as_ushort(__float2bfloat16(b));
    float ra = a - __bfloat162float(__ushort_as_bfloat16(ha));
    float rb = b - __bfloat162float(__ushort_as_bfloat16(hb));
    unsigned short la = __bfloat16_as_ushort(__float2bfloat16(ra));
    unsigned short lb = __bfloat16_as_ushort(__float2bfloat16(rb));
    hi = ((u32)hb << 16) | ha;
    lo = ((u32)lb << 16) | la;
}

#define LDSM4(r, a) \
    asm volatile("ldmatrix.sync.aligned.m8n8.x4.shared.b16 {%0,%1,%2,%3}, [%4];" \
        : "=r"((r)[0]), "=r"((r)[1]), "=r"((r)[2]), "=r"((r)[3]) : "r"(a))
#define LDSM4T(r, a) \
    asm volatile("ldmatrix.sync.aligned.m8n8.x4.trans.shared.b16 {%0,%1,%2,%3}, [%4];" \
        : "=r"((r)[0]), "=r"((r)[1]), "=r"((r)[2]), "=r"((r)[3]) : "r"(a))
#define MMA(c, a, b0, b1) \
    asm volatile("mma.sync.aligned.m16n8k16.row.col.f32.bf16.bf16.f32 " \
        "{%0,%1,%2,%3}, {%4,%5,%6,%7}, {%8,%9}, {%0,%1,%2,%3};" \
        : "+f"((c)[0]), "+f"((c)[1]), "+f"((c)[2]), "+f"((c)[3]) \
        : "r"((a)[0]), "r"((a)[1]), "r"((a)[2]), "r"((a)[3]), "r"(b0), "r"(b1))
#define CP16(dst, src) \
    asm volatile("cp.async.cg.shared.global [%0], [%1], 16;" :: "r"(dst), "l"(src))
#define CP_COMMIT() asm volatile("cp.async.commit_group;")
#define CP_WAIT0()  asm volatile("cp.async.wait_group 0;")

__global__ __launch_bounds__(NTH, 1)
void fa_mma_kernel(const float* __restrict__ Qg, const float* __restrict__ Kg,
                   const float* __restrict__ Vg, float* __restrict__ Og) {
    extern __shared__ char smem[];
    const u32 sb = smem_u32(smem);
    const int tid = threadIdx.x, wid = tid >> 5, lane = tid & 31;

    const size_t hoff = (size_t)blockIdx.y * SEQ * DD;
    const float* Qh = Qg + hoff + (size_t)blockIdx.x * BM * DD;
    const float* Kh = Kg + hoff;
    const float* Vh = Vg + hoff;
    float*       Oh = Og + hoff + (size_t)blockIdx.x * BM * DD;

    // ---- prologue: stage K0/V0 via cp.async; fill Q (LDG) meanwhile ----
    {
        #pragma unroll
        for (int t = 0; t < 8; t++) {
            int i = tid + t * NTH;
            CP16(sb + SM_STG + i * 16,         ((const float4*)Kh) + i);
            CP16(sb + SM_STG + 32768 + i * 16, ((const float4*)Vh) + i);
        }
        CP_COMMIT();

        const float4* G4 = (const float4*)Qh;
        #pragma unroll
        for (int t = 0; t < 16; t++) {
            int i = tid + t * NTH;
            int row = i >> 5, col0 = (i & 31) * 4;
            float4 v = G4[i];
            u32 h0, l0, h1, l1;
            split2(v.x, v.y, h0, l0);
            split2(v.z, v.w, h1, l1);
            u32 a = swz(row, col0, 4);
            *(uint2*)(smem + SM_QHI + a) = make_uint2(h0, h1);
            *(uint2*)(smem + SM_QLO + a) = make_uint2(l0, l1);
        }
        CP_WAIT0();
        __syncthreads();
        // convert staged K0/V0 -> bf16 hi/lo tiles
        const float4* S4 = (const float4*)(smem + SM_STG);
        #pragma unroll
        for (int t = 0; t < 8; t++) {
            int i = tid + t * NTH;
            int row = i >> 5, col0 = (i & 31) * 4;
            u32 a = swz(row, col0, 3);
            float4 v = S4[i];
            u32 h0, lo0, h1, lo1;
            split2(v.x, v.y, h0, lo0);
            split2(v.z, v.w, h1, lo1);
            *(uint2*)(smem + SM_KHI + a) = make_uint2(h0, h1);
            *(uint2*)(smem + SM_KLO + a) = make_uint2(lo0, lo1);
            float4 w = S4[2048 + i];
            split2(w.x, w.y, h0, lo0);
            split2(w.z, w.w, h1, lo1);
            *(uint2*)(smem + SM_VHI + a) = make_uint2(h0, h1);
            *(uint2*)(smem + SM_VLO + a) = make_uint2(lo0, lo1);
        }
        __syncthreads();
    }

    float oacc[16][4];
    #pragma unroll
    for (int n = 0; n < 16; n++)
        #pragma unroll
        for (int c = 0; c < 4; c++) oacc[n][c] = 0.0f;

    float m0 = -1e30f, m1 = -1e30f, l0s = 0.0f, l1s = 0.0f;

    const int frow  = (lane & 7) + ((lane >> 3) & 1) * 8;
    const int fcol8 = ((lane >> 4) & 1) * 8;
    const int qrow  = wid * 16 + frow;

    for (int kt = 0; kt < NT; kt++) {
        // ---- issue staged prefetch of (kt+1): hidden behind this tile's compute ----
        if (kt + 1 < NT) {
            const float4* K4 = (const float4*)(Kh + (size_t)(kt + 1) * BN * DD);
            const float4* V4 = (const float4*)(Vh + (size_t)(kt + 1) * BN * DD);
            #pragma unroll
            for (int t = 0; t < 8; t++) {
                int i = tid + t * NTH;
                CP16(sb + SM_STG + i * 16,         K4 + i);
                CP16(sb + SM_STG + 32768 + i * 16, V4 + i);
            }
            CP_COMMIT();
        }

        // ---- S = Q K^T : units (kk,ng), double-buffered K frags ----
        float sacc[8][4];
        #pragma unroll
        for (int j = 0; j < 8; j++)
            #pragma unroll
            for (int c = 0; c < 4; c++) sacc[j][c] = 0.0f;

        {
            u32 ah[4], al[4], bh[2][4], bl[2][4];
            // prime: A(kk=0), B(kk=0,ng=0)
            {
                u32 qa = sb + SM_QHI + swz(qrow, fcol8, 4);
                LDSM4(ah, qa);
                LDSM4(al, qa + (SM_QLO - SM_QHI));
                u32 ka = sb + SM_KHI + swz(frow, fcol8, 3);
                LDSM4(bh[0], ka);
                LDSM4(bl[0], ka + (SM_KLO - SM_KHI));
            }
            #pragma unroll
            for (int kk = 0; kk < 8; kk++) {
                #pragma unroll
                for (int ng = 0; ng < 4; ng++) {
                    int cur = ng & 1, nxt = cur ^ 1;
                    // prefetch next unit's B (and next kk's A at ng boundary)
                    if (ng < 3) {
                        u32 ka = sb + SM_KHI + swz((ng + 1) * 16 + frow, kk * 16 + fcol8, 3);
                        LDSM4(bh[nxt], ka);
                        LDSM4(bl[nxt], ka + (SM_KLO - SM_KHI));
                    } else if (kk < 7) {
                        u32 ka = sb + SM_KHI + swz(frow, (kk + 1) * 16 + fcol8, 3);
                        LDSM4(bh[nxt], ka);
                        LDSM4(bl[nxt], ka + (SM_KLO - SM_KHI));
                    }
                    MMA(sacc[2 * ng],     ah, bh[cur][0], bh[cur][2]);
                    MMA(sacc[2 * ng],     al, bh[cur][0], bh[cur][2]);
                    MMA(sacc[2 * ng],     ah, bl[cur][0], bl[cur][2]);
                    MMA(sacc[2 * ng + 1], ah, bh[cur][1], bh[cur][3]);
                    MMA(sacc[2 * ng + 1], al, bh[cur][1], bh[cur][3]);
                    MMA(sacc[2 * ng + 1], ah, bl[cur][1], bl[cur][3]);
                }
                if (kk < 7) {
                    u32 qa = sb + SM_QHI + swz(qrow, (kk + 1) * 16 + fcol8, 4);
                    LDSM4(ah, qa);
                    LDSM4(al, qa + (SM_QLO - SM_QHI));
                }
            }
        }

        // ---- online softmax ----
        float mx0 = m0, mx1 = m1;
        #pragma unroll
        for (int j = 0; j < 8; j++) {
            mx0 = fmaxf(mx0, fmaxf(sacc[j][0], sacc[j][1]));
            mx1 = fmaxf(mx1, fmaxf(sacc[j][2], sacc[j][3]));
        }
        mx0 = fmaxf(mx0, __shfl_xor_sync(0xffffffffu, mx0, 1));
        mx0 = fmaxf(mx0, __shfl_xor_sync(0xffffffffu, mx0, 2));
        mx1 = fmaxf(mx1, __shfl_xor_sync(0xffffffffu, mx1, 1));
        mx1 = fmaxf(mx1, __shfl_xor_sync(0xffffffffu, mx1, 2));
        float alpha0 = __expf((m0 - mx0) * SCALE_INV);
        float alpha1 = __expf((m1 - mx1) * SCALE_INV);

        float sum0 = 0.0f, sum1 = 0.0f;
        u32 ph[8][2], pl[8][2];
        #pragma unroll
        for (int j = 0; j < 8; j++) {
            float p0 = __expf((sacc[j][0] - mx0) * SCALE_INV);
            float p1 = __expf((sacc[j][1] - mx0) * SCALE_INV);
            float p2 = __expf((sacc[j][2] - mx1) * SCALE_INV);
            float p3 = __expf((sacc[j][3] - mx1) * SCALE_INV);
            sum0 += p0 + p1;
            sum1 += p2 + p3;
            split2(p0, p1, ph[j][0], pl[j][0]);
            split2(p2, p3, ph[j][1], pl[j][1]);
        }
        sum0 += __shfl_xor_sync(0xffffffffu, sum0, 1);
        sum0 += __shfl_xor_sync(0xffffffffu, sum0, 2);
        sum1 += __shfl_xor_sync(0xffffffffu, sum1, 1);
        sum1 += __shfl_xor_sync(0xffffffffu, sum1, 2);
        l0s = l0s * alpha0 + sum0;
        l1s = l1s * alpha1 + sum1;
        m0 = mx0; m1 = mx1;

        #pragma unroll
        for (int n = 0; n < 16; n++) {
            oacc[n][0] *= alpha0; oacc[n][1] *= alpha0;
            oacc[n][2] *= alpha1; oacc[n][3] *= alpha1;
        }

        // ---- O += P V : units (kk,ng), double-buffered V frags ----
        {
            u32 vh[2][4], vl[2][4];
            {
                u32 va = sb + SM_VHI + swz(frow, fcol8, 3);
                LDSM4T(vh[0], va);
                LDSM4T(vl[0], va + (SM_VLO - SM_VHI));
            }
            #pragma unroll
            for (int kk = 0; kk < 4; kk++) {
                u32 pah[4] = {ph[2*kk][0], ph[2*kk][1], ph[2*kk+1][0], ph[2*kk+1][1]};
                u32 pal[4] = {pl[2*kk][0], pl[2*kk][1], pl[2*kk+1][0], pl[2*kk+1][1]};
                #pragma unroll
                for (int ng = 0; ng < 8; ng++) {
                    int u   = kk * 8 + ng;
                    int cur = u & 1, nxt = cur ^ 1;
                    if (u < 31) {
                        int u1 = u + 1;
                        int kk1 = u1 >> 3, ng1 = u1 & 7;
                        u32 va = sb + SM_VHI + swz(kk1 * 16 + frow, ng1 * 16 + fcol8, 3);
                        LDSM4T(vh[nxt], va);
                        LDSM4T(vl[nxt], va + (SM_VLO - SM_VHI));
                    }
                    MMA(oacc[2*ng],     pah, vh[cur][0], vh[cur][1]);
                    MMA(oacc[2*ng],     pal, vh[cur][0], vh[cur][1]);
                    MMA(oacc[2*ng],     pah, vl[cur][0], vl[cur][1]);
                    MMA(oacc[2*ng + 1], pah, vh[cur][2], vh[cur][3]);
                    MMA(oacc[2*ng + 1], pal, vh[cur][2], vh[cur][3]);
                    MMA(oacc[2*ng + 1], pah, vl[cur][2], vl[cur][3]);
                }
            }
        }

        // ---- convert staged (kt+1) -> bf16 tiles ----
        if (kt + 1 < NT) {
            CP_WAIT0();
            __syncthreads();
            const float4* S4 = (const float4*)(smem + SM_STG);
            #pragma unroll
            for (int t = 0; t < 8; t++) {
                int i = tid + t * NTH;
                int row = i >> 5, col0 = (i & 31) * 4;
                u32 a = swz(row, col0, 3);
                float4 v = S4[i];
                u32 h0, lo0, h1, lo1;
                split2(v.x, v.y, h0, lo0);
                split2(v.z, v.w, h1, lo1);
                *(uint2*)(smem + SM_KHI + a) = make_uint2(h0, h1);
                *(uint2*)(smem + SM_KLO + a) = make_uint2(lo0, lo1);
                float4 w = S4[2048 + i];
                split2(w.x, w.y, h0, lo0);
                split2(w.z, w.w, h1, lo1);
                *(uint2*)(smem + SM_VHI + a) = make_uint2(h0, h1);
                *(uint2*)(smem + SM_VLO + a) = make_uint2(lo0, lo1);
            }
            __syncthreads();
        }
    }

    // ---- epilogue ----
    float inv0 = 1.0f / l0s, inv1 = 1.0f / l1s;
    int orow0 = wid * 16 + (lane >> 2);
    int orow1 = orow0 + 8;
    #pragma unroll
    for (int n = 0; n < 16; n++) {
        int col = n * 8 + 2 * (lane & 3);
        *(float2*)(Oh + (size_t)orow0 * DD + col) = make_float2(oacc[n][0] * inv0, oacc[n][1] * inv0);
        *(float2*)(Oh + (size_t)orow1 * DD + col) = make_float2(oacc[n][2] * inv1, oacc[n][3] * inv1);
    }
}

extern "C" void kernel_launch(void* const* d_in, const int* in_sizes, int n_in,
                              void* d_out, int out_size) {
    const float* Q = (const float*)d_in[0];
    const float* K = (const float*)d_in[1];
    const float* V = (const float*)d_in[2];
    float* O = (float*)d_out;

    cudaFuncSetAttribute(fa_mma_kernel,
                         cudaFuncAttributeMaxDynamicSharedMemorySize, SM_TOTAL);

    dim3 grid(SEQ / BM, 64 /* B*H */);
    fa_mma_kernel<<<grid, NTH, SM_TOTAL>>>(Q, K, V, O);
}